// round 16
// baseline (speedup 1.0000x reference)
#include <cuda_runtime.h>
#include <cooperative_groups.h>
#include <float.h>

namespace cg = cooperative_groups;

// -------- scratch (no allocations; overwritten each replay before use) --------
#define MAXS 32768
#define MAXC 65536
#define MAXT 128      // max scan tiles (MAXS/256)
#define MAXG 4096     // max grid blocks
__device__ int                g_off     [MAXS + 1]; // exclusive prefix sum + sentinel
__device__ int                g_chunkseg[MAXC];     // chunk -> containing segment
__device__ int                g_tilesum [MAXT];     // per-tile scope totals
__device__ unsigned long long g_tden[MAXS];         // fixed-point (2^34) Σ e^t
__device__ unsigned long long g_msum[MAXS];         // fixed-point Σ e^m
__device__ unsigned long long g_dot [MAXS];         // fixed-point Σ e^t * m
__device__ float              g_blocksum[MAXG];     // per-block CE partials

#define SCALE     17179869184.0   // 2^34
#define INV_SCALE 0x1p-34f        // exact power-of-two

// ---- chunk load + exp (offset-independent), proven code ----
__device__ __forceinline__ void load_exp_chunk(
    const float* __restrict__ means, const float* __restrict__ targets,
    int base, int lane, int N, float* e, float* w, float* d)
{
    if (base + 256 <= N) {
        const float4* tp = reinterpret_cast<const float4*>(targets);
        const float4* mp = reinterpret_cast<const float4*>(means);
        const int q = (base >> 2) + lane;
        float4 t0 = tp[q];       float4 t1 = tp[q + 32];
        float4 m0 = mp[q];       float4 m1 = mp[q + 32];
        float tt[8] = {t0.x,t0.y,t0.z,t0.w, t1.x,t1.y,t1.z,t1.w};
        float mm[8] = {m0.x,m0.y,m0.z,m0.w, m1.x,m1.y,m1.z,m1.w};
        #pragma unroll
        for (int j = 0; j < 8; ++j) {
            e[j] = __expf(tt[j]);
            w[j] = __expf(mm[j]);
            d[j] = e[j] * mm[j];
        }
    } else {
        const int pos0 = base + lane * 4;
        const int pos1 = base + 128 + lane * 4;
        #pragma unroll
        for (int j = 0; j < 8; ++j) {
            int p = (j < 4) ? (pos0 + j) : (pos1 + j - 4);
            float tv = (p < N) ? targets[p] : 0.f;
            float mv = (p < N) ? means[p]   : 0.f;
            e[j] = __expf(tv);
            w[j] = __expf(mv);
            d[j] = e[j] * mv;
        }
    }
}

// ============================================================
// ONE cooperative kernel: scan -> map -> stream -> CE, separated
// by hardware grid.sync(). No counters, no polls, no fences.
// ============================================================
__global__ void __launch_bounds__(256)
coop_kernel(const float* __restrict__ means,
            const float* __restrict__ targets,
            const int*   __restrict__ scope,
            float* __restrict__ out,
            int N, int S)
{
    cg::grid_group grid = cg::this_grid();

    const int tid  = threadIdx.x;
    const int lane = tid & 31;
    const int wid  = tid >> 5;                 // 8 warps
    const int B    = gridDim.x;
    const int SB   = (S + 255) >> 8;           // scan tiles

    __shared__ int   s_w[8];
    __shared__ int   s_pre;
    __shared__ float s_red[256];

    // ---------- Phase A1: per-tile scan (intra offsets + tile totals) ----------
    for (int t = blockIdx.x; t < SB; t += B) {
        const int s   = t * 256 + tid;
        const int len = (s < S) ? scope[s] : 0;

        int x = len;
        #pragma unroll
        for (int off = 1; off < 32; off <<= 1) {
            int y = __shfl_up_sync(0xffffffffu, x, off);
            if (lane >= off) x += y;
        }
        if (lane == 31) s_w[wid] = x;
        __syncthreads();
        if (wid == 0) {
            int w = (lane < 8) ? s_w[lane] : 0;
            #pragma unroll
            for (int off = 1; off < 8; off <<= 1) {
                int y = __shfl_up_sync(0xffffffffu, w, off);
                if (lane >= off) w += y;
            }
            if (lane < 8) s_w[lane] = w;
        }
        __syncthreads();

        const int intra = ((wid == 0) ? 0 : s_w[wid - 1]) + (x - len);
        if (s < S) g_off[s] = intra;            // temporarily intra-only
        if (tid == 0) g_tilesum[t] = s_w[7];
        __syncthreads();
    }

    grid.sync();

    // ---------- Phase A2: add tile prefixes; fill chunk map ----------
    for (int t = blockIdx.x; t < SB; t += B) {
        // block-parallel sum of tilesums [0, t)
        int acc = 0;
        for (int j = tid; j < t; j += 256) acc += g_tilesum[j];
        #pragma unroll
        for (int o = 16; o; o >>= 1) acc += __shfl_xor_sync(0xffffffffu, acc, o);
        if (lane == 0) s_w[wid] = acc;
        __syncthreads();
        if (wid == 0) {
            int v = (lane < 8) ? s_w[lane] : 0;
            #pragma unroll
            for (int o = 4; o; o >>= 1) v += __shfl_xor_sync(0xffffffffu, v, o);
            if (lane == 0) s_pre = v;
        }
        __syncthreads();
        const int pre = s_pre;

        const int s = t * 256 + tid;
        if (s < S) {
            const int len   = scope[s];          // L1 hot
            const int start = pre + g_off[s];
            const int end   = start + len;
            g_off[s] = start;
            if (s == S - 1) g_off[S] = end;      // sentinel (== N)
            for (int c = (start + 255) >> 8; (c << 8) < end; ++c)
                g_chunkseg[c] = s;
        }
        __syncthreads();
    }

    grid.sync();

    // ---------- Phase B: streaming (grid-stride, proven bucketing) ----------
    const int totalWarps = B * 8;
    const int nChunks    = (N + 255) >> 8;

    for (int chunk = blockIdx.x * 8 + wid; chunk < nChunks; chunk += totalWarps) {
        const int base = chunk << 8;

        float e[8], w[8], d[8];
        load_exp_chunk(means, targets, base, lane, N, e, w, d);

        int s = g_chunkseg[chunk];
        const int pos0 = base + lane * 4;
        const int pos1 = base + 128 + lane * 4;
        const int last = min(base + 255, N - 1);

        int lower = g_off[s];
        for (;;) {
            const int next = g_off[s + 1];
            float a = 0.f, bb = 0.f, c = 0.f;
            #pragma unroll
            for (int j = 0; j < 8; ++j) {
                const int p = (j < 4) ? (pos0 + j) : (pos1 + j - 4);
                if (p >= lower && p < next) { a += e[j]; bb += w[j]; c += d[j]; }
            }
            #pragma unroll
            for (int o = 16; o; o >>= 1) {
                a  += __shfl_xor_sync(0xffffffffu, a,  o);
                bb += __shfl_xor_sync(0xffffffffu, bb, o);
                c  += __shfl_xor_sync(0xffffffffu, c,  o);
            }
            if (lane == 0) {
                atomicAdd(&g_tden[s], (unsigned long long)__double2ll_rn((double)a  * SCALE));
                atomicAdd(&g_msum[s], (unsigned long long)__double2ll_rn((double)bb * SCALE));
                atomicAdd(&g_dot [s], (unsigned long long)__double2ll_rn((double)c  * SCALE));
            }
            if (next > last) break;
            lower = next;
            ++s;
        }
    }

    grid.sync();

    // ---------- Phase C: inline CE + deterministic reduce ----------
    float part = 0.f;
    for (int seg = blockIdx.x * 256 + tid; seg < S; seg += B * 256) {
        long long tdq = (long long)g_tden[seg];
        if (tdq > 0) {
            float td = __ll2float_rn(tdq);                                  // scale cancels
            float ms = __ll2float_rn((long long)g_msum[seg]) * INV_SCALE;
            float dt = __ll2float_rn((long long)g_dot [seg]);
            part += dt / td - __logf(ms);
        }
        g_tden[seg] = 0ull; g_msum[seg] = 0ull; g_dot[seg] = 0ull;   // reset for next replay
    }
    // fixed-order block tree reduce
    s_red[tid] = part;
    __syncthreads();
    #pragma unroll
    for (int st = 128; st; st >>= 1) {
        if (tid < st) s_red[tid] += s_red[tid + st];
        __syncthreads();
    }
    if (tid == 0) g_blocksum[blockIdx.x] = s_red[0];     // distinct addresses

    grid.sync();

    // block 0: deterministic final reduce over B partials
    if (blockIdx.x == 0) {
        float acc = 0.f;
        for (int j = tid; j < B; j += 256) acc += g_blocksum[j];   // fixed order
        s_red[tid] = acc;
        __syncthreads();
        #pragma unroll
        for (int st = 128; st; st >>= 1) {
            if (tid < st) s_red[tid] += s_red[tid + st];
            __syncthreads();
        }
        if (tid == 0) out[0] = -s_red[0] / (float)S;
    }
}

// ============================================================
extern "C" void kernel_launch(void* const* d_in, const int* in_sizes, int n_in,
                              void* d_out, int out_size)
{
    const float* means   = (const float*)d_in[0];
    const int*   scope   = (const int*)  d_in[1];
    const float* targets = (const float*)d_in[2];
    const int N = in_sizes[0];
    const int S = in_sizes[1];

    // cooperative grid: exactly the max co-resident block count
    int dev = 0;
    cudaGetDevice(&dev);
    int sms = 0;
    cudaDeviceGetAttribute(&sms, cudaDevAttrMultiProcessorCount, dev);
    int bpm = 0;
    cudaOccupancyMaxActiveBlocksPerMultiprocessor(&bpm, coop_kernel, 256, 0);
    if (sms <= 0) sms = 148;
    if (bpm <= 0) bpm = 1;
    int grid = sms * bpm;
    if (grid > MAXG) grid = MAXG;
    const int nChB = (N + 2047) >> 11;           // blocks at 1 chunk/warp
    if (grid > nChB && nChB > 0) grid = nChB;    // don't oversize for small N
    const int SB = (S + 255) >> 8;
    if (grid < SB) grid = SB;                    // (loops handle it anyway)

    cudaLaunchConfig_t cfg = {};
    cfg.gridDim  = dim3(grid, 1, 1);
    cfg.blockDim = dim3(256, 1, 1);
    cfg.stream   = 0;
    cudaLaunchAttribute attr[1];
    attr[0].id = cudaLaunchAttributeCooperative;
    attr[0].val.cooperative = 1;
    cfg.attrs    = attr;
    cfg.numAttrs = 1;

    float* out = (float*)d_out;
    cudaLaunchKernelEx(&cfg, coop_kernel, means, targets, scope, out, N, S);
}

// round 17
// speedup vs baseline: 1.2305x; 1.2305x over previous
#include <cuda_runtime.h>
#include <float.h>

// -------- scratch (no allocations; zero-init; ce_kernel resets) --------
#define MAXS 32768
#define MAXC 65536
#define MAXB 32                                    // max scan blocks (MAXS/1024)
__device__ int                g_off     [MAXS + 1]; // exclusive prefix sum + sentinel
__device__ int                g_chunkseg[MAXC];     // 256-chunk -> containing segment
__device__ int                g_tilesum [MAXB];     // per-block scope totals
__device__ unsigned long long g_tden[MAXS];         // fixed-point (2^34) Σ e^t
__device__ unsigned long long g_msum[MAXS];         // fixed-point Σ e^m
__device__ unsigned long long g_dot [MAXS];         // fixed-point Σ e^t * m
__device__ unsigned long long g_acc;                // fixed-point global Σ ce
__device__ unsigned int       g_scnt;               // scan phase-1 arrivals
__device__ unsigned int       g_done;               // finished-block counter (ce)

#define SCALE     17179869184.0   // 2^34
#define INV_SCALE 0x1p-34f        // exact power-of-two

__device__ __forceinline__ unsigned int load_acquire_u32(const unsigned int* p) {
    unsigned int v;
    asm volatile("ld.global.acquire.gpu.b32 %0, [%1];" : "=r"(v) : "l"(p) : "memory");
    return v;
}

// ============================================================
// Kernel 1 (R12 version — fastest measured): multi-block scan+map.
// ============================================================
__global__ void __launch_bounds__(1024)
scan_map_kernel(const int* __restrict__ scope, int S, int N)
{
    __shared__ int s_w[32];
    const int tid  = threadIdx.x;
    const int lane = tid & 31;
    const int wid  = tid >> 5;
    const int b    = blockIdx.x;
    const int s    = b * 1024 + tid;
    const int B    = gridDim.x;

    // ---- phase 1: intra-block exclusive scan ----
    const int len = (s < S) ? scope[s] : 0;

    int x = len;
    #pragma unroll
    for (int off = 1; off < 32; off <<= 1) {
        int y = __shfl_up_sync(0xffffffffu, x, off);
        if (lane >= off) x += y;
    }
    if (lane == 31) s_w[wid] = x;
    __syncthreads();
    if (wid == 0) {
        int w = s_w[lane];
        #pragma unroll
        for (int off = 1; off < 32; off <<= 1) {
            int y = __shfl_up_sync(0xffffffffu, w, off);
            if (lane >= off) w += y;
        }
        s_w[lane] = w;
    }
    __syncthreads();

    const int intra_excl = ((wid == 0) ? 0 : s_w[wid - 1]) + (x - len);
    const int block_tot  = s_w[31];

    if (tid == 0) {
        g_tilesum[b] = block_tot;
        __threadfence();
        atomicAdd(&g_scnt, 1u);
    }
    if (tid == 0) {
        while (load_acquire_u32(&g_scnt) < (unsigned int)B) { __nanosleep(64); }
    }
    __syncthreads();

    int tile_prefix = 0;
    for (int j = 0; j < b; ++j) tile_prefix += g_tilesum[j];

    if (s < S) {
        const int start = tile_prefix + intra_excl;
        const int end   = start + len;
        g_off[s] = start;
        if (s == S - 1) g_off[S] = end;       // sentinel (== N)
        for (int c = (start + 255) >> 8; (c << 8) < end; ++c)
            g_chunkseg[c] = s;
    }
}

// ============================================================
// Kernel 2: one WARP per 512-element super-chunk.
// 16 front-batched float4 loads per array (MLP 16), fewer warps,
// fewer per-segment atomic triples. NO tail/fence/single-address.
// ============================================================
__global__ void __launch_bounds__(256)
main_kernel(const float* __restrict__ means,
            const float* __restrict__ targets,
            int N, int S)
{
    const int lane = threadIdx.x & 31;
    const int warp = (blockIdx.x * 256 + threadIdx.x) >> 5;
    const int base = warp * 512;
    if (base >= N) return;

    int s = g_chunkseg[base >> 8];

    float e[16], w[16], d[16];
    if (base + 512 <= N) {
        const float4* tp = reinterpret_cast<const float4*>(targets);
        const float4* mp = reinterpret_cast<const float4*>(means);
        const int q = (base >> 2) + lane;
        float4 t0 = tp[q];       float4 t1 = tp[q + 32];
        float4 t2 = tp[q + 64];  float4 t3 = tp[q + 96];
        float4 m0 = mp[q];       float4 m1 = mp[q + 32];
        float4 m2 = mp[q + 64];  float4 m3 = mp[q + 96];
        float tt[16] = {t0.x,t0.y,t0.z,t0.w, t1.x,t1.y,t1.z,t1.w,
                        t2.x,t2.y,t2.z,t2.w, t3.x,t3.y,t3.z,t3.w};
        float mm[16] = {m0.x,m0.y,m0.z,m0.w, m1.x,m1.y,m1.z,m1.w,
                        m2.x,m2.y,m2.z,m2.w, m3.x,m3.y,m3.z,m3.w};
        #pragma unroll
        for (int j = 0; j < 16; ++j) {
            e[j] = __expf(tt[j]);
            w[j] = __expf(mm[j]);
            d[j] = e[j] * mm[j];
        }
    } else {
        #pragma unroll
        for (int j = 0; j < 16; ++j) {
            const int p = base + ((j >> 2) << 7) + lane * 4 + (j & 3);
            float tv = (p < N) ? targets[p] : 0.f;
            float mv = (p < N) ? means[p]   : 0.f;
            e[j] = __expf(tv);
            w[j] = __expf(mv);
            d[j] = e[j] * mv;
        }
    }

    const int last = min(base + 511, N - 1);
    int lower = g_off[s];
    for (;;) {
        const int next = g_off[s + 1];  // sentinel guarantees validity
        float a = 0.f, b = 0.f, c = 0.f;
        #pragma unroll
        for (int j = 0; j < 16; ++j) {
            const int p = base + ((j >> 2) << 7) + lane * 4 + (j & 3);
            if (p >= lower && p < next) { a += e[j]; b += w[j]; c += d[j]; }
        }
        #pragma unroll
        for (int o = 16; o; o >>= 1) {
            a += __shfl_xor_sync(0xffffffffu, a, o);
            b += __shfl_xor_sync(0xffffffffu, b, o);
            c += __shfl_xor_sync(0xffffffffu, c, o);
        }
        if (lane == 0) {
            atomicAdd(&g_tden[s], (unsigned long long)__double2ll_rn((double)a * SCALE));
            atomicAdd(&g_msum[s], (unsigned long long)__double2ll_rn((double)b * SCALE));
            atomicAdd(&g_dot [s], (unsigned long long)__double2ll_rn((double)c * SCALE));
        }
        if (next > last) break;
        lower = next;
        ++s;
    }
}

// ============================================================
// Kernel 3: per-segment CE (fp32), 128x128 for wider SM spread.
// ============================================================
__global__ void __launch_bounds__(128)
ce_kernel(float* __restrict__ out, int S)
{
    const int tid  = threadIdx.x;
    const int lane = tid & 31;
    const int wid  = tid >> 5;           // 4 warps
    const int seg  = blockIdx.x * 128 + tid;

    float ce = 0.f;
    if (seg < S) {
        long long tdq = (long long)g_tden[seg];
        float td = __ll2float_rn(tdq);                                 // 2^34 scale cancels
        float ms = __ll2float_rn((long long)g_msum[seg]) * INV_SCALE;  // exact pow2 scale
        float dt = __ll2float_rn((long long)g_dot [seg]);
        if (tdq > 0) ce = dt / td - __logf(ms);
        g_tden[seg] = 0ull; g_msum[seg] = 0ull; g_dot[seg] = 0ull;     // reset for next replay
    }

    __shared__ float sm[4];
    float v = ce;
    #pragma unroll
    for (int o = 16; o; o >>= 1) v += __shfl_xor_sync(0xffffffffu, v, o);
    if (lane == 0) sm[wid] = v;
    __syncthreads();
    if (wid == 0) {
        v = (lane < 4) ? sm[lane] : 0.f;
        #pragma unroll
        for (int o = 2; o; o >>= 1) v += __shfl_xor_sync(0xffffffffu, v, o);
        if (lane == 0) {
            atomicAdd(&g_acc, (unsigned long long)__double2ll_rn((double)v * SCALE));
            __threadfence();
            unsigned int prev = atomicAdd(&g_done, 1u);
            if (prev == gridDim.x - 1) {
                unsigned long long tot = atomicAdd(&g_acc, 0ull);
                double sum = (double)(long long)tot / SCALE;
                out[0] = (float)(-sum / (double)S);
                g_acc  = 0ull;   // reset for next replay
                g_done = 0u;
                g_scnt = 0u;     // re-arm scan handshake
                __threadfence();
            }
        }
    }
}

// ============================================================
extern "C" void kernel_launch(void* const* d_in, const int* in_sizes, int n_in,
                              void* d_out, int out_size)
{
    const float* means   = (const float*)d_in[0];
    const int*   scope   = (const int*)  d_in[1];
    const float* targets = (const float*)d_in[2];
    const int N = in_sizes[0];
    const int S = in_sizes[1];

    const int scanBlocks = (S + 1023) / 1024;
    scan_map_kernel<<<scanBlocks, 1024>>>(scope, S, N);

    const int nWarps  = (N + 511) / 512;
    const int nBlocks = (nWarps + 7) / 8;
    main_kernel<<<nBlocks, 256>>>(means, targets, N, S);

    ce_kernel<<<(S + 127) / 128, 128>>>((float*)d_out, S);
}